// round 1
// baseline (speedup 1.0000x reference)
#include <cuda_runtime.h>
#include <cstdint>
#include <cstddef>

// Attend_62534723830373: out = softmax(causal(K V^T / sqrt(128))) @ V
// (reference computes scores from k and v; q is unused.)
// Shapes: [2,16,2048,128] fp32. Flash-attention, TF32 mma.sync (m16n8k8).

namespace {

constexpr int S        = 2048;
constexpr int D        = 128;
constexpr int NBH      = 32;     // b*h
constexpr int BM       = 64;     // query rows per CTA
constexpr int BN       = 64;     // kv rows per iteration
constexpr int NTHREADS = 128;    // 4 warps, each owns 16 query rows
constexpr float SCALE_F = 0.08838834764831845f;

// SMEM strides in 32-bit words; stride % 32 == 4 keeps fragment LDS conflict-free
constexpr int KSTR = 132;
constexpr int VSTR = 132;
constexpr int PSTR = 68;
constexpr int SMEM_WORDS = BM * KSTR + BN * VSTR + BM * PSTR;
constexpr int SMEM_BYTES = SMEM_WORDS * 4;   // 84992 bytes -> 2 CTAs/SM

__device__ __forceinline__ uint32_t f2tf32(float f) {
    uint32_t u;
    asm("cvt.rna.tf32.f32 %0, %1;" : "=r"(u) : "f"(f));
    return u;
}

// D(16x8) += A(16x8,row) * B(8x8,col), tf32 inputs, fp32 accum
__device__ __forceinline__ void mma8(float* c,
                                     uint32_t a0, uint32_t a1, uint32_t a2, uint32_t a3,
                                     uint32_t b0, uint32_t b1) {
    asm volatile(
        "mma.sync.aligned.m16n8k8.row.col.f32.tf32.tf32.f32 "
        "{%0,%1,%2,%3}, {%4,%5,%6,%7}, {%8,%9}, {%0,%1,%2,%3};"
        : "+f"(c[0]), "+f"(c[1]), "+f"(c[2]), "+f"(c[3])
        : "r"(a0), "r"(a1), "r"(a2), "r"(a3), "r"(b0), "r"(b1));
}

__global__ __launch_bounds__(NTHREADS)
void fa_tf32_kernel(const float* __restrict__ Kg,
                    const float* __restrict__ Vg,
                    float* __restrict__ Og) {
    extern __shared__ uint32_t smem[];
    uint32_t* sK = smem;                         // [BM][KSTR], scale folded, tf32
    uint32_t* sV = smem + BM * KSTR;             // [BN][VSTR], tf32
    uint32_t* sP = smem + BM * KSTR + BN * VSTR; // [BM][PSTR], tf32 softmax probs

    const int tid  = threadIdx.x;
    const int warp = tid >> 5;
    const int lane = tid & 31;
    const int g    = lane >> 2;   // group id (row within 8-row half)
    const int tg   = lane & 3;    // thread-in-group (k / paired-col index)

    const int bh = blockIdx.y;
    const int qb = (int)gridDim.x - 1 - (int)blockIdx.x;  // longest CTAs first

    const float* Kh = Kg + (size_t)bh * S * D;
    const float* Vh = Vg + (size_t)bh * S * D;
    float*       Oh = Og + (size_t)bh * S * D;

    // ---- preload K block (scaled, tf32) ----
    {
        const float4* src = reinterpret_cast<const float4*>(Kh + (size_t)qb * BM * D);
        for (int i = tid; i < BM * D / 4; i += NTHREADS) {
            float4 q4 = src[i];
            uint32_t* dst = sK + (i >> 5) * KSTR + ((i & 31) << 2);  // 32 float4 per row
            dst[0] = f2tf32(q4.x * SCALE_F);
            dst[1] = f2tf32(q4.y * SCALE_F);
            dst[2] = f2tf32(q4.z * SCALE_F);
            dst[3] = f2tf32(q4.w * SCALE_F);
        }
    }

    const int r0  = warp * 16 + g;     // local row (this thread's first row)
    const int gi0 = qb * BM + r0;      // global row
    const int gi1 = gi0 + 8;

    float oacc[16][4];                 // O tile: 16 n-tiles across D=128
    #pragma unroll
    for (int nt = 0; nt < 16; ++nt) {
        oacc[nt][0] = 0.f; oacc[nt][1] = 0.f; oacc[nt][2] = 0.f; oacc[nt][3] = 0.f;
    }
    float m0 = -1e30f, m1 = -1e30f, l0 = 0.f, l1 = 0.f;

    for (int jb = 0; jb <= qb; ++jb) {
        __syncthreads();   // previous iteration's sV readers are done
        // ---- load V block jb (tf32) ----
        {
            const float4* src = reinterpret_cast<const float4*>(Vh + (size_t)jb * BN * D);
            for (int i = tid; i < BN * D / 4; i += NTHREADS) {
                float4 v4 = src[i];
                uint32_t* dst = sV + (i >> 5) * VSTR + ((i & 31) << 2);
                dst[0] = f2tf32(v4.x);
                dst[1] = f2tf32(v4.y);
                dst[2] = f2tf32(v4.z);
                dst[3] = f2tf32(v4.w);
            }
        }
        __syncthreads();

        // ---- GEMM1: S(16x64) = K'(16x128) * V^T ----
        float sacc[8][4];
        #pragma unroll
        for (int nt = 0; nt < 8; ++nt) {
            sacc[nt][0] = 0.f; sacc[nt][1] = 0.f; sacc[nt][2] = 0.f; sacc[nt][3] = 0.f;
        }
        #pragma unroll
        for (int kt = 0; kt < D / 8; ++kt) {
            const int k0 = kt * 8;
            const uint32_t* kr = sK + r0 * KSTR + k0;
            const uint32_t a0 = kr[tg];
            const uint32_t a1 = kr[8 * KSTR + tg];
            const uint32_t a2 = kr[tg + 4];
            const uint32_t a3 = kr[8 * KSTR + tg + 4];
            #pragma unroll
            for (int nt = 0; nt < 8; ++nt) {
                const uint32_t* vr = sV + (nt * 8 + g) * VSTR + k0;
                mma8(sacc[nt], a0, a1, a2, a3, vr[tg], vr[tg + 4]);
            }
        }

        // ---- online softmax ----
        const bool diag  = (jb == qb);
        const int  jcol0 = jb * BN + 2 * tg;
        float rmax0 = -1e30f, rmax1 = -1e30f;
        #pragma unroll
        for (int nt = 0; nt < 8; ++nt) {
            if (diag) {
                const int jc = jcol0 + nt * 8;
                if (jc     > gi0) sacc[nt][0] = -1e30f;
                if (jc + 1 > gi0) sacc[nt][1] = -1e30f;
                if (jc     > gi1) sacc[nt][2] = -1e30f;
                if (jc + 1 > gi1) sacc[nt][3] = -1e30f;
            }
            rmax0 = fmaxf(rmax0, fmaxf(sacc[nt][0], sacc[nt][1]));
            rmax1 = fmaxf(rmax1, fmaxf(sacc[nt][2], sacc[nt][3]));
        }
        rmax0 = fmaxf(rmax0, __shfl_xor_sync(0xffffffffu, rmax0, 1));
        rmax0 = fmaxf(rmax0, __shfl_xor_sync(0xffffffffu, rmax0, 2));
        rmax1 = fmaxf(rmax1, __shfl_xor_sync(0xffffffffu, rmax1, 1));
        rmax1 = fmaxf(rmax1, __shfl_xor_sync(0xffffffffu, rmax1, 2));

        const float mn0 = fmaxf(m0, rmax0);
        const float mn1 = fmaxf(m1, rmax1);
        const float al0 = __expf(m0 - mn0);
        const float al1 = __expf(m1 - mn1);
        m0 = mn0; m1 = mn1;

        float rs0 = 0.f, rs1 = 0.f;
        uint32_t* pw = sP + r0 * PSTR + 2 * tg;
        #pragma unroll
        for (int nt = 0; nt < 8; ++nt) {
            const float p0 = __expf(sacc[nt][0] - mn0);
            const float p1 = __expf(sacc[nt][1] - mn0);
            const float p2 = __expf(sacc[nt][2] - mn1);
            const float p3 = __expf(sacc[nt][3] - mn1);
            rs0 += p0 + p1;
            rs1 += p2 + p3;
            pw[nt * 8]                = f2tf32(p0);
            pw[nt * 8 + 1]            = f2tf32(p1);
            pw[8 * PSTR + nt * 8]     = f2tf32(p2);
            pw[8 * PSTR + nt * 8 + 1] = f2tf32(p3);
        }
        rs0 += __shfl_xor_sync(0xffffffffu, rs0, 1);
        rs0 += __shfl_xor_sync(0xffffffffu, rs0, 2);
        rs1 += __shfl_xor_sync(0xffffffffu, rs1, 1);
        rs1 += __shfl_xor_sync(0xffffffffu, rs1, 2);
        l0 = l0 * al0 + rs0;
        l1 = l1 * al1 + rs1;

        #pragma unroll
        for (int nt = 0; nt < 16; ++nt) {
            oacc[nt][0] *= al0; oacc[nt][1] *= al0;
            oacc[nt][2] *= al1; oacc[nt][3] *= al1;
        }
        __syncwarp();   // P tile (per-warp region) visible to all lanes

        // ---- GEMM2: O(16x128) += P(16x64) * V(64x128) ----
        #pragma unroll
        for (int kt = 0; kt < BN / 8; ++kt) {
            const int k0 = kt * 8;
            const uint32_t* pr = sP + r0 * PSTR + k0;
            const uint32_t a0 = pr[tg];
            const uint32_t a1 = pr[8 * PSTR + tg];
            const uint32_t a2 = pr[tg + 4];
            const uint32_t a3 = pr[8 * PSTR + tg + 4];
            #pragma unroll
            for (int nt = 0; nt < 16; ++nt) {
                const uint32_t* vc = sV + nt * 8 + g;
                mma8(oacc[nt], a0, a1, a2, a3,
                     vc[(k0 + tg) * VSTR], vc[(k0 + tg + 4) * VSTR]);
            }
        }
    }

    // ---- epilogue: normalize and store ----
    const float inv0 = 1.f / l0;
    const float inv1 = 1.f / l1;
    float* o0 = Oh + (size_t)gi0 * D + 2 * tg;
    float* o1 = Oh + (size_t)gi1 * D + 2 * tg;
    #pragma unroll
    for (int nt = 0; nt < 16; ++nt) {
        float2 w0 = make_float2(oacc[nt][0] * inv0, oacc[nt][1] * inv0);
        float2 w1 = make_float2(oacc[nt][2] * inv1, oacc[nt][3] * inv1);
        *reinterpret_cast<float2*>(o0 + nt * 8) = w0;
        *reinterpret_cast<float2*>(o1 + nt * 8) = w1;
    }
}

}  // namespace

extern "C" void kernel_launch(void* const* d_in, const int* /*in_sizes*/, int /*n_in*/,
                              void* d_out, int /*out_size*/) {
    // inputs: d_in[0]=q (UNUSED by reference), d_in[1]=k, d_in[2]=v
    const float* k = reinterpret_cast<const float*>(d_in[1]);
    const float* v = reinterpret_cast<const float*>(d_in[2]);
    float* o = reinterpret_cast<float*>(d_out);

    cudaFuncSetAttribute(fa_tf32_kernel,
                         cudaFuncAttributeMaxDynamicSharedMemorySize, SMEM_BYTES);
    dim3 grid(S / BM, NBH);
    fa_tf32_kernel<<<grid, NTHREADS, SMEM_BYTES>>>(k, v, o);
}